// round 13
// baseline (speedup 1.0000x reference)
#include <cuda_runtime.h>
#include <cuda_bf16.h>

#define NODES  100000
#define EDGES  1600000
#define F      128
#define NGRAPH 2048
#define SCAN_BLK 1024
#define SCAN_NBLK ((NODES + SCAN_BLK - 1) / SCAN_BLK)   // 98

typedef unsigned long long ull;

// Packed f32x2 helpers (sm_103a FFMA2 — PTX only, ptxas never auto-fuses)
#define FMA2(acc, a, b) \
    asm("fma.rn.f32x2 %0, %1, %2, %0;" : "+l"(acc) : "l"(a), "l"(b))
#define PACK2(out, lo, hi) \
    asm("mov.b64 %0, {%1, %2};" : "=l"(out) : "r"(__float_as_uint(lo)), "r"(__float_as_uint(hi)))
#define UNPACK2(lo, hi, in) \
    asm("mov.b64 {%0, %1}, %2;" : "=r"(lo), "=r"(hi) : "l"(in))

// Scratch (device globals — allocations banned). 16B-aligned for float4.
__device__ __align__(16) float g_xw[NODES * F];    // X@W1
__device__ __align__(16) float g_z[NODES];         // z[n] = h[n]·(W2@Wlin)
__device__ __align__(16) float g_rdeg[NODES];      // rsqrt(deg incl self)
__device__ __align__(16) float g_wt[F];            // w~ = W2 @ Wlin
__device__ __align__(16) float g_pool1[NGRAPH];    // per-graph scalar sums
__device__ __align__(16) float g_cnt[NGRAPH];      // per-graph node counts
__device__ float g_c2;                             // dot(b2, Wlin)
__device__ int g_degi[NODES];                      // in-degree (no self loop)
__device__ int g_rowstart[NODES];                  // CSR row offsets
__device__ int g_fill[NODES];                      // CSR fill cursors (seeded = rowstart)
__device__ int g_csr[EDGES];                       // CSR src indices
__device__ int g_bsum[SCAN_NBLK];
__device__ int g_boff[SCAN_NBLK];
__device__ int g_sel;                              // which 128-vec is Wlin
__device__ int g_ei64;                             // edge_index int64?
__device__ int g_b64;                              // batch int64?

// ---------------------------------------------------------------------------
// Detect index dtypes + identify Wlin (the only nonzero 128-vec).
__global__ void k_inspect(const void* __restrict__ ei,
                          const void* __restrict__ batch,
                          const float* __restrict__ v0,
                          const float* __restrict__ v1,
                          const float* __restrict__ v2) {
    if (blockIdx.x != 0 || threadIdx.x != 0) return;
    const int* e32 = (const int*)ei;
    int allz = 1;
    for (int i = 1; i < 257; i += 2) if (e32[i] != 0) { allz = 0; break; }
    g_ei64 = allz;
    const int* b32 = (const int*)batch;
    allz = 1;
    for (int i = 99489; i < 100000; i += 2) if (b32[i] != 0) { allz = 0; break; }
    g_b64 = allz;
    float s0 = 0.f, s1 = 0.f, s2 = 0.f;
    for (int i = 0; i < 128; i++) {
        s0 += fabsf(v0[i]); s1 += fabsf(v1[i]); s2 += fabsf(v2[i]);
    }
    int s = 0; float m = s0;
    if (s1 > m) { m = s1; s = 1; }
    if (s2 > m) { s = 2; }
    g_sel = s;
}

__device__ __forceinline__ int loadIdx(const void* p, int i, int is64, int n) {
    int x = is64 ? (int)((const long long*)p)[i] : ((const int*)p)[i];
    return ((unsigned)x < (unsigned)n) ? x : 0;
}

// ---------------------------------------------------------------------------
// w~ = W2 @ Wlin  (128-vec) and c2 = dot(b2, Wlin). One block, 128 threads.
__global__ void k_wt(const float* __restrict__ W2,
                     const float* __restrict__ v0,
                     const float* __restrict__ v1,
                     const float* __restrict__ v2) {
    __shared__ float wl[F];
    __shared__ float red[F];
    int t = threadIdx.x;
    const float* wsel[3] = {v0, v1, v2};
    const float* Wlin = wsel[g_sel];
    const float* b2   = wsel[(g_sel + 2) % 3];
    wl[t] = Wlin[t];
    __syncthreads();
    float s = 0.f;
#pragma unroll 8
    for (int j = 0; j < F; j++) s = fmaf(W2[t * F + j], wl[j], s);
    g_wt[t] = s;
    red[t] = b2[t] * wl[t];
    __syncthreads();
    for (int off = 64; off > 0; off >>= 1) {
        if (t < off) red[t] += red[t + off];
        __syncthreads();
    }
    if (t == 0) g_c2 = red[0];
}

// ---------------------------------------------------------------------------
// Init: zero degi/pool1/cnt
__global__ void k_init() {
    int i = blockIdx.x * blockDim.x + threadIdx.x;
    if (i < NODES)  g_degi[i] = 0;
    if (i < NGRAPH) { g_pool1[i] = 0.f; g_cnt[i] = 0.f; }
}

// In-degree histogram + graph node counts (fused)
__global__ void k_deg(const void* __restrict__ ei,
                      const void* __restrict__ batch) {
    int e = blockIdx.x * blockDim.x + threadIdx.x;
    if (e < EDGES) atomicAdd(&g_degi[loadIdx(ei, EDGES + e, g_ei64, NODES)], 1);
    if (e < NODES) atomicAdd(&g_cnt[loadIdx(batch, e, g_b64, NGRAPH)], 1.f);
}

// ---------------------------------------------------------------------------
// Multi-block exclusive scan of g_degi -> g_rowstart.
__global__ __launch_bounds__(SCAN_BLK) void k_scan1() {
    __shared__ int sh[SCAN_BLK];
    int t = threadIdx.x;
    int i = blockIdx.x * SCAN_BLK + t;
    int v = (i < NODES) ? g_degi[i] : 0;
    sh[t] = v;
    __syncthreads();
    for (int off = 1; off < SCAN_BLK; off <<= 1) {
        int add = (t >= off) ? sh[t - off] : 0;
        __syncthreads();
        sh[t] += add;
        __syncthreads();
    }
    if (i < NODES) g_rowstart[i] = sh[t] - v;   // exclusive (pre-offset)
    if (t == SCAN_BLK - 1) g_bsum[blockIdx.x] = sh[t];
}

__global__ void k_scan2() {
    if (threadIdx.x != 0) return;
    int run = 0;
    for (int i = 0; i < SCAN_NBLK; i++) {
        g_boff[i] = run;
        run += g_bsum[i];
    }
}

// Apply block offsets; compute rdeg; seed fill cursors with rowstart.
__global__ __launch_bounds__(SCAN_BLK) void k_scan3() {
    int i = blockIdx.x * SCAN_BLK + threadIdx.x;
    if (i >= NODES) return;
    int rs = g_rowstart[i] + g_boff[blockIdx.x];
    g_rowstart[i] = rs;
    g_fill[i] = rs;
    g_rdeg[i] = rsqrtf((float)g_degi[i] + 1.0f);
}

// CSR fill: csr[cursor[dst]++] = src   (cursor pre-seeded with rowstart)
__global__ void k_fill(const void* __restrict__ ei) {
    int e = blockIdx.x * blockDim.x + threadIdx.x;
    if (e >= EDGES) return;
    int is64 = g_ei64;
    int s = loadIdx(ei, e, is64, NODES);
    int d = loadIdx(ei, EDGES + e, is64, NODES);
    int pos = atomicAdd(&g_fill[d], 1);
    g_csr[pos] = s;
}

// ---------------------------------------------------------------------------
// GEMM1: g_xw = X[N,128] @ W1[128,128], packed FFMA2 with zero in-loop packs.
// Xsd holds broadcast pairs (x,x) per element (packed once at load).
// W column-pairs (W[k][c],W[k][c+1]) are natural 64-bit words in the Ws row.
// 256 thr, tile 32 rows x 128 cols, full K in smem. 48KB static smem.
__global__ __launch_bounds__(256) void k_gemm(const float* __restrict__ X,
                                              const float* __restrict__ W) {
    __shared__ ull   Xsd[32][128];   // 32KB: (x,x) pairs, full K=128
    __shared__ float Ws[32][128];    // 16KB: one 32-k chunk of W

    int tx = threadIdx.x & 31;   // cols tx*4..tx*4+3
    int ty = threadIdx.x >> 5;   // rows ty*4..ty*4+3
    int rowBase = blockIdx.x * 32;

    // Load X tile, duplicating each float into a 64-bit (x,x) pair.
    for (int i = threadIdx.x; i < 32 * 32; i += 256) {
        int r = i >> 5;
        int c = (i & 31) * 4;
        float4 v = make_float4(0.f, 0.f, 0.f, 0.f);
        int gr = rowBase + r;
        if (gr < NODES) v = *(const float4*)&X[gr * F + c];
        ull p;
        PACK2(p, v.x, v.x); Xsd[r][c]     = p;
        PACK2(p, v.y, v.y); Xsd[r][c + 1] = p;
        PACK2(p, v.z, v.z); Xsd[r][c + 2] = p;
        PACK2(p, v.w, v.w); Xsd[r][c + 3] = p;
    }

    // acc2[r][0]=(c0,c1), acc2[r][1]=(c2,c3)
    ull acc2[4][2];
#pragma unroll
    for (int r = 0; r < 4; r++) { acc2[r][0] = 0ull; acc2[r][1] = 0ull; }

    for (int kk = 0; kk < 128; kk += 32) {
        __syncthreads();
        for (int i = threadIdx.x; i < 32 * 32; i += 256) {
            int r = i >> 5;
            int c = (i & 31) * 4;
            *(float4*)&Ws[r][c] = *(const float4*)&W[(kk + r) * F + c];
        }
        __syncthreads();
#pragma unroll
        for (int k = 0; k < 32; k += 2) {
            // w pairs: one LDS.128 per k covers both column-pairs
            ulonglong2 wA = *(const ulonglong2*)&Ws[k][tx * 4];
            ulonglong2 wB = *(const ulonglong2*)&Ws[k + 1][tx * 4];
#pragma unroll
            for (int r = 0; r < 4; r++) {
                // broadcast pairs for k and k+1: one LDS.128
                ulonglong2 xr = *(const ulonglong2*)&Xsd[ty * 4 + r][kk + k];
                FMA2(acc2[r][0], xr.x, wA.x);
                FMA2(acc2[r][1], xr.x, wA.y);
                FMA2(acc2[r][0], xr.y, wB.x);
                FMA2(acc2[r][1], xr.y, wB.y);
            }
        }
    }

#pragma unroll
    for (int r = 0; r < 4; r++) {
        int gr = rowBase + ty * 4 + r;
        if (gr < NODES) {
            unsigned int o0, o1, o2, o3;
            UNPACK2(o0, o1, acc2[r][0]);
            UNPACK2(o2, o3, acc2[r][1]);
            *(float4*)&g_xw[gr * F + tx * 4] =
                make_float4(__uint_as_float(o0), __uint_as_float(o1),
                            __uint_as_float(o2), __uint_as_float(o3));
        }
    }
}

// ---------------------------------------------------------------------------
// Layer-1 aggregate+combine+relu fused directly into z, warp per node:
// h[d] = relu( rdeg[d]*sum_s rdeg[s]*xw[s] + xw[d]/deg[d] + b1 )  (in regs)
// z[d] = dot(h[d], w~)  — h never touches gmem.
__global__ __launch_bounds__(256) void k_agg_relu(const float* __restrict__ v0,
                                                  const float* __restrict__ v1,
                                                  const float* __restrict__ v2) {
    int node = (blockIdx.x * blockDim.x + threadIdx.x) >> 5;
    int lane = threadIdx.x & 31;
    if (node >= NODES) return;
    const float* bsel[3] = {v0, v1, v2};
    const float* b = bsel[(g_sel + 1) % 3];

    int start = g_rowstart[node];
    int n = g_degi[node];
    float4 acc = make_float4(0.f, 0.f, 0.f, 0.f);
    int j = 0;
    for (; j + 1 < n; j += 2) {
        int s0 = g_csr[start + j];
        int s1 = g_csr[start + j + 1];
        float w0 = g_rdeg[s0];
        float w1 = g_rdeg[s1];
        float4 a = *(const float4*)&g_xw[s0 * F + lane * 4];
        float4 c = *(const float4*)&g_xw[s1 * F + lane * 4];
        acc.x += a.x * w0 + c.x * w1;
        acc.y += a.y * w0 + c.y * w1;
        acc.z += a.z * w0 + c.z * w1;
        acc.w += a.w * w0 + c.w * w1;
    }
    if (j < n) {
        int s0 = g_csr[start + j];
        float w0 = g_rdeg[s0];
        float4 a = *(const float4*)&g_xw[s0 * F + lane * 4];
        acc.x += a.x * w0; acc.y += a.y * w0; acc.z += a.z * w0; acc.w += a.w * w0;
    }

    float rd = g_rdeg[node];
    float dinv = rd * rd;            // 1/deg
    float4 xw = *(const float4*)&g_xw[node * F + lane * 4];
    float4 bb = *(const float4*)&b[lane * 4];
    float4 h;
    h.x = fmaxf(acc.x * rd + xw.x * dinv + bb.x, 0.f);
    h.y = fmaxf(acc.y * rd + xw.y * dinv + bb.y, 0.f);
    h.z = fmaxf(acc.z * rd + xw.z * dinv + bb.z, 0.f);
    h.w = fmaxf(acc.w * rd + xw.w * dinv + bb.w, 0.f);

    // z[node] = dot(h[node], w~)
    float4 wt = *(const float4*)&g_wt[lane * 4];
    float zp = h.x * wt.x + h.y * wt.y + h.z * wt.z + h.w * wt.w;
#pragma unroll
    for (int o = 16; o > 0; o >>= 1) zp += __shfl_xor_sync(0xffffffffu, zp, o);
    if (lane == 0) g_z[node] = zp;
}

// ---------------------------------------------------------------------------
// Scalar layer-2: s[n] = rdeg[n]*sum_src rdeg[src]*z[src] + z[n]/deg[n];
// pool1[batch[n]] += s[n]. Thread per node.
__global__ __launch_bounds__(256) void k_agg2(const void* __restrict__ batch) {
    int node = blockIdx.x * blockDim.x + threadIdx.x;
    if (node >= NODES) return;
    int start = g_rowstart[node];
    int n = g_degi[node];
    float acc = 0.f;
#pragma unroll 4
    for (int j = 0; j < n; j++) {
        int s = g_csr[start + j];
        acc += g_z[s] * g_rdeg[s];
    }
    float rd = g_rdeg[node];
    float s = acc * rd + g_z[node] * rd * rd;
    atomicAdd(&g_pool1[loadIdx(batch, node, g_b64, NGRAPH)], s);
}

// ---------------------------------------------------------------------------
// Final: out[g] = pool1[g]/max(cnt,1) + c2 + blin
__global__ void k_final(const float* __restrict__ blin,
                        float* __restrict__ out) {
    int g = blockIdx.x * blockDim.x + threadIdx.x;
    if (g >= NGRAPH) return;
    out[g] = g_pool1[g] / fmaxf(g_cnt[g], 1.f) + g_c2 + blin[0];
}

// ---------------------------------------------------------------------------
extern "C" void kernel_launch(void* const* d_in, const int* in_sizes, int n_in,
                              void* d_out, int out_size) {
    const float* x     = nullptr;
    const void*  ei    = nullptr;
    const void*  batch = nullptr;
    const float* W1    = nullptr;
    const float* W2    = nullptr;
    const float* blin  = nullptr;
    const float* v128[3] = {nullptr, nullptr, nullptr};
    int n128 = 0;

    for (int i = 0; i < n_in; i++) {
        switch (in_sizes[i]) {
            case NODES * F:   x = (const float*)d_in[i];   break;
            case 2 * EDGES:   ei = d_in[i];                break;
            case NODES:       batch = d_in[i];             break;
            case F * F:       if (!W1) W1 = (const float*)d_in[i];
                              else     W2 = (const float*)d_in[i]; break;
            case F:           if (n128 < 3) v128[n128++] = (const float*)d_in[i]; break;
            case 1:           blin = (const float*)d_in[i]; break;
            default: break;
        }
    }
    float* out = (float*)d_out;

    const int edgeGrid = (EDGES + 255) / 256;
    const int nodeGrid = (NODES + 255) / 256;
    const int warpNodeGrid = (NODES * 32 + 255) / 256;  // warp per node
    const int gemmGrid = (NODES + 31) / 32;

    k_inspect<<<1, 32>>>(ei, batch, v128[0], v128[1], v128[2]);
    k_wt<<<1, 128>>>(W2, v128[0], v128[1], v128[2]);
    k_init<<<nodeGrid, 256>>>();
    k_deg<<<edgeGrid, 256>>>(ei, batch);
    k_scan1<<<SCAN_NBLK, SCAN_BLK>>>();
    k_scan2<<<1, 32>>>();
    k_scan3<<<SCAN_NBLK, SCAN_BLK>>>();
    k_fill<<<edgeGrid, 256>>>(ei);

    // Layer 1: GEMM + aggregate (h in regs, fused into z)
    k_gemm<<<gemmGrid, 256>>>(x, W1);
    k_agg_relu<<<warpNodeGrid, 256>>>(v128[0], v128[1], v128[2]);

    // Layer 2 collapsed to scalar aggregation + pooling
    k_agg2<<<nodeGrid, 256>>>(batch);

    k_final<<<(NGRAPH + 255) / 256, 256>>>(blin, out);
}